// round 1
// baseline (speedup 1.0000x reference)
#include <cuda_runtime.h>
#include <math.h>

#define B     16
#define Hf    1024
#define Wf    1024
#define HS    512
#define HC    256
#define NCH   32
#define KTOP  32
#define CROPS 160
#define THRESH 0.2f

// ---------------- device scratch (no allocs allowed) ----------------
__device__ float g_imgs[B * HS * HS];                     // 16.8 MB resized
__device__ float g_h[B * NCH * HC * HC];                  // 134 MB conv1 out, NCHW
__device__ float g_cms[B * HC * HC];                      // 4.2 MB confmaps
__device__ unsigned long long g_keys[B * HC * HC];        // 8.4 MB peak keys
__device__ int   g_cnt[B];
__device__ float g_selval[B * KTOP];
__device__ int   g_selidx[B * KTOP];
__device__ float g_cx[B * KTOP];
__device__ float g_cy[B * KTOP];
__device__ float g_validf[B * KTOP];

// ---------------- zero counters ----------------
__global__ void k_zero() {
    if (threadIdx.x < B) g_cnt[threadIdx.x] = 0;
}

// ---------------- antialiased bilinear resize 1024->512 ----------------
// taps r = 2o-1+t, t=0..3, w = {.25,.75,.75,.25}, OOB->0, renormalize per axis
__global__ void k_resize(const float* __restrict__ full) {
    int t = blockIdx.x * blockDim.x + threadIdx.x;
    if (t >= B * HS * HS) return;
    int x = t % HS;
    int y = (t / HS) % HS;
    int b = t / (HS * HS);

    float wy[4], wx[4];
    int ry[4], rx[4];
    float sy = 0.f, sx = 0.f;
#pragma unroll
    for (int i = 0; i < 4; i++) {
        int r = 2 * y - 1 + i;
        float w = (i == 0 || i == 3) ? 0.25f : 0.75f;
        if (r < 0 || r >= Hf) w = 0.f;
        ry[i] = r < 0 ? 0 : (r >= Hf ? Hf - 1 : r);
        wy[i] = w; sy += w;
        int c = 2 * x - 1 + i;
        float w2 = (i == 0 || i == 3) ? 0.25f : 0.75f;
        if (c < 0 || c >= Wf) w2 = 0.f;
        rx[i] = c < 0 ? 0 : (c >= Wf ? Wf - 1 : c);
        wx[i] = w2; sx += w2;
    }
    float inv = 1.f / (sy * sx);
    const float* im = full + (size_t)b * Hf * Wf;
    float acc = 0.f;
#pragma unroll
    for (int i = 0; i < 4; i++) {
        const float* row = im + (size_t)ry[i] * Wf;
        float racc = 0.f;
#pragma unroll
        for (int j = 0; j < 4; j++) racc += wx[j] * row[rx[j]];
        acc += wy[i] * racc;
    }
    g_imgs[t] = acc * inv;
}

// ---------------- conv1: 5x5x1->32, stride 2, SAME(1,2), ReLU ----------------
// 2x2 output micro-tile per thread, channel groups of 8 (4 FMA per weight LDS)
__device__ __forceinline__ float ld_img(const float* img, int iy, int ix) {
    if ((unsigned)iy >= HS || (unsigned)ix >= HS) return 0.f;
    return img[iy * HS + ix];
}

__global__ void k_conv1(const float* __restrict__ w1, const float* __restrict__ b1) {
    __shared__ float sw[800];
    __shared__ float sb[NCH];
    int tid = threadIdx.y * blockDim.x + threadIdx.x;   // 128 threads
    for (int i = tid; i < 800; i += 128) sw[i] = w1[i];
    if (tid < NCH) sb[tid] = b1[tid];
    __syncthreads();

    int x0 = blockIdx.x * 32 + threadIdx.x * 2;   // blockDim (16,8)
    int y0 = blockIdx.y * 16 + threadIdx.y * 2;
    int b  = blockIdx.z;
    const float* img = g_imgs + (size_t)b * HS * HS;

    int iy_base = 2 * y0 - 1;
    int ix_base = 2 * x0 - 1;

    for (int cg = 0; cg < 4; cg++) {
        float a00[8], a01[8], a10[8], a11[8];
#pragma unroll
        for (int c = 0; c < 8; c++) { a00[c] = 0.f; a01[c] = 0.f; a10[c] = 0.f; a11[c] = 0.f; }
#pragma unroll
        for (int k = 0; k < 5; k++) {
            int iy = iy_base + k;
#pragma unroll
            for (int l = 0; l < 5; l++) {
                int ix = ix_base + l;
                float v00 = ld_img(img, iy,     ix);
                float v01 = ld_img(img, iy,     ix + 2);
                float v10 = ld_img(img, iy + 2, ix);
                float v11 = ld_img(img, iy + 2, ix + 2);
                const float* wp = sw + (k * 5 + l) * NCH + cg * 8;
#pragma unroll
                for (int c = 0; c < 8; c++) {
                    float w = wp[c];
                    a00[c] += v00 * w; a01[c] += v01 * w;
                    a10[c] += v10 * w; a11[c] += v11 * w;
                }
            }
        }
#pragma unroll
        for (int c = 0; c < 8; c++) {
            int ch = cg * 8 + c;
            float bias = sb[ch];
            float r00 = fmaxf(a00[c] + bias, 0.f);
            float r01 = fmaxf(a01[c] + bias, 0.f);
            float r10 = fmaxf(a10[c] + bias, 0.f);
            float r11 = fmaxf(a11[c] + bias, 0.f);
            float* hp = g_h + ((size_t)(b * NCH + ch) * HC + y0) * HC + x0;
            hp[0] = r00; hp[1] = r01;
            hp[HC] = r10; hp[HC + 1] = r11;
        }
    }
}

// ---------------- conv2: 5x5x32->1, stride 1, SAME(2,2), sigmoid ----------------
// block (32,8): 32x32 output tile, each thread 4 rows; per-channel 36x36 smem tile
__global__ void k_conv2(const float* __restrict__ w2, const float* __restrict__ b2) {
    __shared__ float sw[800];
    __shared__ float tile[36 * 36];
    int tid = threadIdx.y * 32 + threadIdx.x;   // 256 threads
    for (int i = tid; i < 800; i += 256) sw[i] = w2[i];
    float bias = b2[0];

    int b  = blockIdx.z;
    int x  = blockIdx.x * 32 + threadIdx.x;
    int yb = blockIdx.y * 32 + threadIdx.y * 4;
    int gy0 = blockIdx.y * 32 - 2;
    int gx0 = blockIdx.x * 32 - 2;

    float acc[4] = {0.f, 0.f, 0.f, 0.f};

    for (int c = 0; c < NCH; c++) {
        const float* plane = g_h + (size_t)(b * NCH + c) * HC * HC;
        __syncthreads();  // protect tile from previous iteration's readers (+ sw on iter 0)
        for (int i = tid; i < 1296; i += 256) {
            int r  = i / 36, cc = i % 36;
            int gy = gy0 + r, gx = gx0 + cc;
            float v = 0.f;
            if ((unsigned)gy < HC && (unsigned)gx < HC) v = plane[gy * HC + gx];
            tile[i] = v;
        }
        __syncthreads();

        float wr[25];
#pragma unroll
        for (int m = 0; m < 25; m++) wr[m] = sw[m * NCH + c];

#pragma unroll
        for (int dl = 0; dl < 5; dl++) {
            float t[8];
#pragma unroll
            for (int r = 0; r < 8; r++)
                t[r] = tile[(threadIdx.y * 4 + r) * 36 + threadIdx.x + dl];
#pragma unroll
            for (int dy = 0; dy < 5; dy++) {
                float w = wr[dy * 5 + dl];
#pragma unroll
                for (int jy = 0; jy < 4; jy++) acc[jy] += t[jy + dy] * w;
            }
        }
    }
#pragma unroll
    for (int jy = 0; jy < 4; jy++) {
        float z = acc[jy] + bias;
        float s = 1.f / (1.f + expf(-z));
        g_cms[(b * HC + yb + jy) * HC + x] = s;
    }
}

// ---------------- NMS (3x3, >= with -inf SAME pad) + peak compaction ----------------
__global__ void k_nms() {
    int t = blockIdx.x * blockDim.x + threadIdx.x;
    if (t >= B * HC * HC) return;
    float v = g_cms[t];
    if (!(v > THRESH)) return;
    int x = t % HC;
    int y = (t / HC) % HC;
    int b = t / (HC * HC);
    const float* c = g_cms + b * HC * HC;
    bool peak = true;
#pragma unroll
    for (int dy = -1; dy <= 1; dy++)
#pragma unroll
        for (int dx = -1; dx <= 1; dx++) {
            if (dy == 0 && dx == 0) continue;
            int ny = y + dy, nx = x + dx;
            if ((unsigned)ny < HC && (unsigned)nx < HC)
                if (c[ny * HC + nx] > v) peak = false;
        }
    if (!peak) return;
    int p = atomicAdd(&g_cnt[b], 1);
    unsigned idx = (unsigned)(y * HC + x);
    unsigned long long key =
        ((unsigned long long)__float_as_uint(v) << 32) | (0xFFFFFFFFu - idx);
    g_keys[b * HC * HC + p] = key;
}

// ---------------- exact top-K (descending, lower-idx tie-break) ----------------
__global__ void k_topk() {
    __shared__ unsigned long long sk[256];
    __shared__ int sp[256];
    int b = blockIdx.x, tid = threadIdx.x;
    int n = g_cnt[b];
    unsigned long long* keys = g_keys + b * HC * HC;

    for (int s = 0; s < KTOP; s++) {
        unsigned long long best = 0ULL; int bp = -1;
        for (int i = tid; i < n; i += 256) {
            unsigned long long k = keys[i];
            if (k > best) { best = k; bp = i; }
        }
        sk[tid] = best; sp[tid] = bp;
        __syncthreads();
        for (int off = 128; off > 0; off >>= 1) {
            if (tid < off && sk[tid + off] > sk[tid]) {
                sk[tid] = sk[tid + off]; sp[tid] = sp[tid + off];
            }
            __syncthreads();
        }
        if (tid == 0) {
            if (sk[0] == 0ULL) {
                g_selidx[b * KTOP + s] = -1;
                g_selval[b * KTOP + s] = 0.f;
            } else {
                keys[sp[0]] = 0ULL;  // exclude from later passes
                unsigned long long k = sk[0];
                g_selval[b * KTOP + s] = __uint_as_float((unsigned)(k >> 32));
                g_selidx[b * KTOP + s] = (int)(0xFFFFFFFFu - (unsigned)(k & 0xFFFFFFFFu));
            }
        }
        __syncthreads();
    }
}

// ---------------- 5x5 integral refinement + extras output ----------------
__global__ void k_refine(float* __restrict__ out, int out_size) {
    int i = blockIdx.x * blockDim.x + threadIdx.x;
    if (i >= B * KTOP) return;
    int b = i / KTOP;
    int idx = g_selidx[i];
    float cx, cy, val, vf;
    if (idx < 0) {
        cx = (float)CROPS * 0.5f; cy = (float)CROPS * 0.5f; val = 0.f; vf = 0.f;
    } else {
        val = g_selval[i]; vf = 1.f;
        int py = idx / HC, px = idx % HC;
        const float* c = g_cms + b * HC * HC;
        float gv = 0.f, sx = 0.f, sy = 0.f;
#pragma unroll
        for (int oy = -2; oy <= 2; oy++)
#pragma unroll
            for (int ox = -2; ox <= 2; ox++) {
                int yy = py + oy, xx = px + ox;
                float p = 0.f;
                if ((unsigned)yy < HC && (unsigned)xx < HC) p = c[yy * HC + xx];
                gv += p; sx += p * (float)ox; sy += p * (float)oy;
            }
        gv += 1e-12f;
        float dx = sx / gv, dy = sy / gv;
        cx = ((float)px + dx) * 4.f;   // * CM_STRIDE / SCALE
        cy = ((float)py + dy) * 4.f;
    }
    g_cx[i] = cx; g_cy[i] = cy; g_validf[i] = vf;

    const int OFFC = B * KTOP * CROPS * CROPS;       // 13,107,200
    if (out_size >= OFFC + B * KTOP * 4) {
        out[OFFC + i * 2 + 0] = cx - (float)CROPS * 0.5f;   // crop_offsets x
        out[OFFC + i * 2 + 1] = cy - (float)CROPS * 0.5f;   // crop_offsets y
        out[OFFC + B * KTOP * 2 + i] = val;                 // centroid_vals
        out[OFFC + B * KTOP * 3 + i] = vf;                  // valid
    }
}

// ---------------- bilinear 160x160 crops from the full image ----------------
__global__ void k_crop(const float* __restrict__ full, float* __restrict__ out) {
    int bk = blockIdx.x;              // 0..511
    int b = bk / KTOP;
    float cx = g_cx[bk], cy = g_cy[bk], vf = g_validf[bk];
    float bx = cx - (float)(CROPS - 1) * 0.5f;
    float by = cy - (float)(CROPS - 1) * 0.5f;
    const float* im = full + (size_t)b * Hf * Wf;
    float* o = out + (size_t)bk * CROPS * CROPS;

    for (int t = threadIdx.x; t < CROPS * CROPS; t += blockDim.x) {
        int i = t / CROPS, j = t % CROPS;
        float sy = by + (float)i;
        float sx = bx + (float)j;
        float y0 = floorf(sy), x0 = floorf(sx);
        float wy = sy - y0,   wx = sx - x0;
        int yi = (int)y0, xi = (int)x0;
        int y0c = min(max(yi, 0), Hf - 1);
        int y1c = min(max(yi + 1, 0), Hf - 1);
        int x0c = min(max(xi, 0), Wf - 1);
        int x1c = min(max(xi + 1, 0), Wf - 1);
        float a = im[y0c * Wf + x0c];
        float bb = im[y0c * Wf + x1c];
        float cc = im[y1c * Wf + x0c];
        float dd = im[y1c * Wf + x1c];
        float top = a * (1.f - wx) + bb * wx;
        float bot = cc * (1.f - wx) + dd * wx;
        float r = top * (1.f - wy) + bot * wy;
        bool inr = (sy >= 0.f) && (sy <= (float)(Hf - 1)) &&
                   (sx >= 0.f) && (sx <= (float)(Wf - 1));
        o[t] = (inr ? r : 0.f) * vf;
    }
}

// ---------------- launcher ----------------
extern "C" void kernel_launch(void* const* d_in, const int* in_sizes, int n_in,
                              void* d_out, int out_size) {
    const float* full = (const float*)d_in[0];
    const float* w1   = (const float*)d_in[1];
    const float* b1   = (const float*)d_in[2];
    const float* w2   = (const float*)d_in[3];
    const float* b2   = (const float*)d_in[4];
    float* out = (float*)d_out;

    k_zero<<<1, 32>>>();
    k_resize<<<(B * HS * HS + 255) / 256, 256>>>(full);
    k_conv1<<<dim3(HC / 32, HC / 16, B), dim3(16, 8)>>>(w1, b1);
    k_conv2<<<dim3(HC / 32, HC / 32, B), dim3(32, 8)>>>(w2, b2);
    k_nms<<<(B * HC * HC + 255) / 256, 256>>>();
    k_topk<<<B, 256>>>();
    k_refine<<<2, 256>>>(out, out_size);
    k_crop<<<B * KTOP, 256>>>(full, out);
}

// round 2
// speedup vs baseline: 1.2838x; 1.2838x over previous
#include <cuda_runtime.h>
#include <math.h>

#define B     16
#define Hf    1024
#define Wf    1024
#define HS    512
#define HC    256
#define NCH   32
#define KTOP  32
#define CROPS 160
#define THRESH 0.2f

typedef unsigned long long u64;

// ---------------- device scratch (no allocs allowed) ----------------
__device__ float g_imgs[B * HS * HS];                     // 16.8 MB resized
__device__ float g_cms[B * HC * HC];                      // 4.2 MB confmaps
__device__ unsigned long long g_keys[B * HC * HC];        // 8.4 MB peak keys
__device__ int   g_cnt[B];
__device__ float g_selval[B * KTOP];
__device__ int   g_selidx[B * KTOP];
__device__ float g_cx[B * KTOP];
__device__ float g_cy[B * KTOP];
__device__ float g_validf[B * KTOP];

// ---------------- f32x2 helpers (Blackwell packed fp32 FMA) ----------------
__device__ __forceinline__ u64 ffma2(u64 a, u64 b, u64 c) {
    u64 d;
    asm("fma.rn.f32x2 %0, %1, %2, %3;" : "=l"(d) : "l"(a), "l"(b), "l"(c));
    return d;
}
__device__ __forceinline__ u64 pack2(float x, float y) {
    u64 d; asm("mov.b64 %0, {%1, %2};" : "=l"(d) : "f"(x), "f"(y)); return d;
}
__device__ __forceinline__ void unpack2(u64 v, float& x, float& y) {
    asm("mov.b64 {%0, %1}, %2;" : "=f"(x), "=f"(y) : "l"(v));
}

// ---------------- zero counters ----------------
__global__ void k_zero() {
    if (threadIdx.x < B) g_cnt[threadIdx.x] = 0;
}

// ---------------- antialiased bilinear resize 1024->512 ----------------
__global__ void k_resize(const float* __restrict__ full) {
    int t = blockIdx.x * blockDim.x + threadIdx.x;
    if (t >= B * HS * HS) return;
    int x = t % HS;
    int y = (t / HS) % HS;
    int b = t / (HS * HS);

    float wy[4], wx[4];
    int ry[4], rx[4];
    float sy = 0.f, sx = 0.f;
#pragma unroll
    for (int i = 0; i < 4; i++) {
        int r = 2 * y - 1 + i;
        float w = (i == 0 || i == 3) ? 0.25f : 0.75f;
        if (r < 0 || r >= Hf) w = 0.f;
        ry[i] = r < 0 ? 0 : (r >= Hf ? Hf - 1 : r);
        wy[i] = w; sy += w;
        int c = 2 * x - 1 + i;
        float w2 = (i == 0 || i == 3) ? 0.25f : 0.75f;
        if (c < 0 || c >= Wf) w2 = 0.f;
        rx[i] = c < 0 ? 0 : (c >= Wf ? Wf - 1 : c);
        wx[i] = w2; sx += w2;
    }
    float inv = 1.f / (sy * sx);
    const float* im = full + (size_t)b * Hf * Wf;
    float acc = 0.f;
#pragma unroll
    for (int i = 0; i < 4; i++) {
        const float* row = im + (size_t)ry[i] * Wf;
        float racc = 0.f;
#pragma unroll
        for (int j = 0; j < 4; j++) racc += wx[j] * row[rx[j]];
        acc += wy[i] * racc;
    }
    g_imgs[t] = acc * inv;
}

// ---------------- fused conv1 (5x5x1->32 s2 ReLU) + conv2 (5x5x32->1 sigmoid) ---
// One CTA per 32x32 cms tile. 256 threads.
// smem: w1[800] | b1[32] | w2[800] | partial[8*1024] | hplanes[32][1296]
// Step1: 18x18 blocks of 2x2 h-positions, channel-pair packed FFMA2.
// Step2: thread = (col, chgroup): 32 rows x 4 channels, cross-warp reduce.
#define SM_W1   0
#define SM_B1   800
#define SM_W2   832
#define SM_PART 1632
#define SM_HPL  9824
#define SM_FLOATS (9824 + 32 * 1296)   // 51296 floats = 205184 bytes

__global__ void __launch_bounds__(256) k_fused(
        const float* __restrict__ w1, const float* __restrict__ b1,
        const float* __restrict__ w2, const float* __restrict__ b2) {
    extern __shared__ float sm[];
    float* sw1 = sm + SM_W1;
    float* sb1 = sm + SM_B1;
    float* sw2 = sm + SM_W2;
    float* spart = sm + SM_PART;
    float* hpl = sm + SM_HPL;

    int tid = threadIdx.x;
    for (int i = tid; i < 800; i += 256) { sw1[i] = w1[i]; sw2[i] = w2[i]; }
    if (tid < 32) sb1[tid] = b1[tid];
    __syncthreads();

    int bx = blockIdx.x, by = blockIdx.y, b = blockIdx.z;
    const float* img = g_imgs + (size_t)b * HS * HS;

    // ---------- step 1: h halo tile 36x36 x 32ch ----------
    for (int blk = tid; blk < 324; blk += 256) {
        int br = blk / 18, bc = blk % 18;
        int hy0 = by * 32 - 2 + 2 * br;
        int hx0 = bx * 32 - 2 + 2 * bc;
        int iy0 = 2 * hy0 - 1, ix0 = 2 * hx0 - 1;   // 7x7 input patch

        float p[7][7];
        bool inb = (iy0 >= 0) && (iy0 + 6 < HS) && (ix0 >= 0) && (ix0 + 6 < HS);
        if (inb) {
#pragma unroll
            for (int r = 0; r < 7; r++) {
                const float* row = img + (iy0 + r) * HS + ix0;
#pragma unroll
                for (int c = 0; c < 7; c++) p[r][c] = row[c];
            }
        } else {
#pragma unroll
            for (int r = 0; r < 7; r++) {
                int iy = iy0 + r;
                bool rv = (unsigned)iy < HS;
#pragma unroll
                for (int c = 0; c < 7; c++) {
                    int ix = ix0 + c;
                    p[r][c] = (rv && (unsigned)ix < HS) ? img[iy * HS + ix] : 0.f;
                }
            }
        }

        // validity of the 4 h positions (conv2 zero-pads outside [0,256))
        bool pv[4];
        pv[0] = ((unsigned)(hy0) < HC) && ((unsigned)(hx0) < HC);
        pv[1] = ((unsigned)(hy0) < HC) && ((unsigned)(hx0 + 1) < HC);
        pv[2] = ((unsigned)(hy0 + 1) < HC) && ((unsigned)(hx0) < HC);
        pv[3] = ((unsigned)(hy0 + 1) < HC) && ((unsigned)(hx0 + 1) < HC);

        for (int cg = 0; cg < 4; cg++) {
            u64 a0[4], a1[4], a2[4], a3[4];
#pragma unroll
            for (int cp = 0; cp < 4; cp++) {
                a0[cp] = 0ULL; a1[cp] = 0ULL; a2[cp] = 0ULL; a3[cp] = 0ULL;
            }
#pragma unroll
            for (int k = 0; k < 5; k++) {
#pragma unroll
                for (int l = 0; l < 5; l++) {
                    u64 v00 = pack2(p[k][l],         p[k][l]);
                    u64 v01 = pack2(p[k][l + 2],     p[k][l + 2]);
                    u64 v10 = pack2(p[k + 2][l],     p[k + 2][l]);
                    u64 v11 = pack2(p[k + 2][l + 2], p[k + 2][l + 2]);
                    const float* wp = sw1 + (k * 5 + l) * 32 + cg * 8;
#pragma unroll
                    for (int cp = 0; cp < 4; cp++) {
                        u64 wv = *reinterpret_cast<const u64*>(wp + cp * 2);
                        a0[cp] = ffma2(v00, wv, a0[cp]);
                        a1[cp] = ffma2(v01, wv, a1[cp]);
                        a2[cp] = ffma2(v10, wv, a2[cp]);
                        a3[cp] = ffma2(v11, wv, a3[cp]);
                    }
                }
            }
            int tr = 2 * br, tc = 2 * bc;
#pragma unroll
            for (int cp = 0; cp < 4; cp++) {
                int ch = cg * 8 + cp * 2;
                float bb0 = sb1[ch], bb1 = sb1[ch + 1];
                float lo, hi;
                float* h0p = hpl + ch * 1296;
                float* h1p = hpl + (ch + 1) * 1296;

                unpack2(a0[cp], lo, hi);
                h0p[tr * 36 + tc] = pv[0] ? fmaxf(lo + bb0, 0.f) : 0.f;
                h1p[tr * 36 + tc] = pv[0] ? fmaxf(hi + bb1, 0.f) : 0.f;
                unpack2(a1[cp], lo, hi);
                h0p[tr * 36 + tc + 1] = pv[1] ? fmaxf(lo + bb0, 0.f) : 0.f;
                h1p[tr * 36 + tc + 1] = pv[1] ? fmaxf(hi + bb1, 0.f) : 0.f;
                unpack2(a2[cp], lo, hi);
                h0p[(tr + 1) * 36 + tc] = pv[2] ? fmaxf(lo + bb0, 0.f) : 0.f;
                h1p[(tr + 1) * 36 + tc] = pv[2] ? fmaxf(hi + bb1, 0.f) : 0.f;
                unpack2(a3[cp], lo, hi);
                h0p[(tr + 1) * 36 + tc + 1] = pv[3] ? fmaxf(lo + bb0, 0.f) : 0.f;
                h1p[(tr + 1) * 36 + tc + 1] = pv[3] ? fmaxf(hi + bb1, 0.f) : 0.f;
            }
        }
    }
    __syncthreads();

    // ---------- step 2: conv2, thread = (col tx, channel-group tg) ----------
    {
        int tx = tid & 31;
        int tg = tid >> 5;
        float acc[32];
#pragma unroll
        for (int r = 0; r < 32; r++) acc[r] = 0.f;

        for (int c = 0; c < 4; c++) {
            int ch = tg * 4 + c;
            const float* hp = hpl + ch * 1296 + tx;
            for (int dl = 0; dl < 5; dl++) {
                float t[36];
#pragma unroll
                for (int r = 0; r < 36; r++) t[r] = hp[r * 36 + dl];
#pragma unroll
                for (int dy = 0; dy < 5; dy++) {
                    float w = sw2[(dy * 5 + dl) * 32 + ch];
#pragma unroll
                    for (int jy = 0; jy < 32; jy++) acc[jy] += t[jy + dy] * w;
                }
            }
        }
#pragma unroll
        for (int r = 0; r < 32; r++) spart[tg * 1024 + r * 32 + tx] = acc[r];
    }
    __syncthreads();

    // ---------- reduce 8 groups + bias + sigmoid ----------
    {
        float bias = b2[0];
        for (int i = tid; i < 1024; i += 256) {
            float s = bias;
#pragma unroll
            for (int g = 0; g < 8; g++) s += spart[g * 1024 + i];
            float z = 1.f / (1.f + expf(-s));
            int r = i >> 5, cc = i & 31;
            g_cms[((size_t)b * HC + (by * 32 + r)) * HC + (bx * 32 + cc)] = z;
        }
    }
}

// ---------------- NMS (3x3) + peak compaction ----------------
__global__ void k_nms() {
    int t = blockIdx.x * blockDim.x + threadIdx.x;
    if (t >= B * HC * HC) return;
    float v = g_cms[t];
    if (!(v > THRESH)) return;
    int x = t % HC;
    int y = (t / HC) % HC;
    int b = t / (HC * HC);
    const float* c = g_cms + b * HC * HC;
    bool peak = true;
#pragma unroll
    for (int dy = -1; dy <= 1; dy++)
#pragma unroll
        for (int dx = -1; dx <= 1; dx++) {
            if (dy == 0 && dx == 0) continue;
            int ny = y + dy, nx = x + dx;
            if ((unsigned)ny < HC && (unsigned)nx < HC)
                if (c[ny * HC + nx] > v) peak = false;
        }
    if (!peak) return;
    int p = atomicAdd(&g_cnt[b], 1);
    unsigned idx = (unsigned)(y * HC + x);
    unsigned long long key =
        ((unsigned long long)__float_as_uint(v) << 32) | (0xFFFFFFFFu - idx);
    g_keys[b * HC * HC + p] = key;
}

// ---------------- exact top-K (descending, lower-idx tie-break) ----------------
__global__ void k_topk() {
    __shared__ unsigned long long sk[256];
    __shared__ int sp[256];
    int b = blockIdx.x, tid = threadIdx.x;
    int n = g_cnt[b];
    unsigned long long* keys = g_keys + b * HC * HC;

    for (int s = 0; s < KTOP; s++) {
        unsigned long long best = 0ULL; int bp = -1;
        for (int i = tid; i < n; i += 256) {
            unsigned long long k = keys[i];
            if (k > best) { best = k; bp = i; }
        }
        sk[tid] = best; sp[tid] = bp;
        __syncthreads();
        for (int off = 128; off > 0; off >>= 1) {
            if (tid < off && sk[tid + off] > sk[tid]) {
                sk[tid] = sk[tid + off]; sp[tid] = sp[tid + off];
            }
            __syncthreads();
        }
        if (tid == 0) {
            if (sk[0] == 0ULL) {
                g_selidx[b * KTOP + s] = -1;
                g_selval[b * KTOP + s] = 0.f;
            } else {
                keys[sp[0]] = 0ULL;
                unsigned long long k = sk[0];
                g_selval[b * KTOP + s] = __uint_as_float((unsigned)(k >> 32));
                g_selidx[b * KTOP + s] = (int)(0xFFFFFFFFu - (unsigned)(k & 0xFFFFFFFFu));
            }
        }
        __syncthreads();
    }
}

// ---------------- 5x5 integral refinement + extras output ----------------
__global__ void k_refine(float* __restrict__ out, int out_size) {
    int i = blockIdx.x * blockDim.x + threadIdx.x;
    if (i >= B * KTOP) return;
    int b = i / KTOP;
    int idx = g_selidx[i];
    float cx, cy, val, vf;
    if (idx < 0) {
        cx = (float)CROPS * 0.5f; cy = (float)CROPS * 0.5f; val = 0.f; vf = 0.f;
    } else {
        val = g_selval[i]; vf = 1.f;
        int py = idx / HC, px = idx % HC;
        const float* c = g_cms + b * HC * HC;
        float gv = 0.f, sx = 0.f, sy = 0.f;
#pragma unroll
        for (int oy = -2; oy <= 2; oy++)
#pragma unroll
            for (int ox = -2; ox <= 2; ox++) {
                int yy = py + oy, xx = px + ox;
                float p = 0.f;
                if ((unsigned)yy < HC && (unsigned)xx < HC) p = c[yy * HC + xx];
                gv += p; sx += p * (float)ox; sy += p * (float)oy;
            }
        gv += 1e-12f;
        float dx = sx / gv, dy = sy / gv;
        cx = ((float)px + dx) * 4.f;
        cy = ((float)py + dy) * 4.f;
    }
    g_cx[i] = cx; g_cy[i] = cy; g_validf[i] = vf;

    const int OFFC = B * KTOP * CROPS * CROPS;
    if (out_size >= OFFC + B * KTOP * 4) {
        out[OFFC + i * 2 + 0] = cx - (float)CROPS * 0.5f;
        out[OFFC + i * 2 + 1] = cy - (float)CROPS * 0.5f;
        out[OFFC + B * KTOP * 2 + i] = val;
        out[OFFC + B * KTOP * 3 + i] = vf;
    }
}

// ---------------- bilinear 160x160 crops from the full image ----------------
__global__ void k_crop(const float* __restrict__ full, float* __restrict__ out) {
    int bk = blockIdx.x;
    int b = bk / KTOP;
    float cx = g_cx[bk], cy = g_cy[bk], vf = g_validf[bk];
    float bx = cx - (float)(CROPS - 1) * 0.5f;
    float by = cy - (float)(CROPS - 1) * 0.5f;
    const float* im = full + (size_t)b * Hf * Wf;
    float* o = out + (size_t)bk * CROPS * CROPS;

    for (int t = threadIdx.x; t < CROPS * CROPS; t += blockDim.x) {
        int i = t / CROPS, j = t % CROPS;
        float sy = by + (float)i;
        float sx = bx + (float)j;
        float y0 = floorf(sy), x0 = floorf(sx);
        float wy = sy - y0,   wx = sx - x0;
        int yi = (int)y0, xi = (int)x0;
        int y0c = min(max(yi, 0), Hf - 1);
        int y1c = min(max(yi + 1, 0), Hf - 1);
        int x0c = min(max(xi, 0), Wf - 1);
        int x1c = min(max(xi + 1, 0), Wf - 1);
        float a = im[y0c * Wf + x0c];
        float bb = im[y0c * Wf + x1c];
        float cc = im[y1c * Wf + x0c];
        float dd = im[y1c * Wf + x1c];
        float top = a * (1.f - wx) + bb * wx;
        float bot = cc * (1.f - wx) + dd * wx;
        float r = top * (1.f - wy) + bot * wy;
        bool inr = (sy >= 0.f) && (sy <= (float)(Hf - 1)) &&
                   (sx >= 0.f) && (sx <= (float)(Wf - 1));
        o[t] = (inr ? r : 0.f) * vf;
    }
}

// ---------------- launcher ----------------
extern "C" void kernel_launch(void* const* d_in, const int* in_sizes, int n_in,
                              void* d_out, int out_size) {
    const float* full = (const float*)d_in[0];
    const float* w1   = (const float*)d_in[1];
    const float* b1   = (const float*)d_in[2];
    const float* w2   = (const float*)d_in[3];
    const float* b2   = (const float*)d_in[4];
    float* out = (float*)d_out;

    const int smem_bytes = SM_FLOATS * 4;   // 205184
    cudaFuncSetAttribute(k_fused, cudaFuncAttributeMaxDynamicSharedMemorySize,
                         smem_bytes);

    k_zero<<<1, 32>>>();
    k_resize<<<(B * HS * HS + 255) / 256, 256>>>(full);
    k_fused<<<dim3(HC / 32, HC / 32, B), 256, smem_bytes>>>(w1, b1, w2, b2);
    k_nms<<<(B * HC * HC + 255) / 256, 256>>>();
    k_topk<<<B, 256>>>();
    k_refine<<<2, 256>>>(out, out_size);
    k_crop<<<B * KTOP, 256>>>(full, out);
}

// round 3
// speedup vs baseline: 1.6141x; 1.2573x over previous
#include <cuda_runtime.h>
#include <math.h>

#define B     16
#define Hf    1024
#define Wf    1024
#define HS    512
#define HC    256
#define NCH   32
#define KTOP  32
#define CROPS 160
#define THRESH 0.2f
#define NCAP  16384   // max peaks/image (independent-set bound on king graph)

typedef unsigned long long u64;

// ---------------- device scratch (no allocs allowed) ----------------
__device__ float g_imgs[B * HS * HS];
__device__ float g_cms[B * HC * HC];
__device__ u64   g_keys[B * HC * HC];
__device__ int   g_cnt[B];
__device__ float g_cx[B * KTOP];
__device__ float g_cy[B * KTOP];
__device__ float g_validf[B * KTOP];

// ---------------- f32x2 helpers ----------------
__device__ __forceinline__ u64 ffma2(u64 a, u64 b, u64 c) {
    u64 d;
    asm("fma.rn.f32x2 %0, %1, %2, %3;" : "=l"(d) : "l"(a), "l"(b), "l"(c));
    return d;
}
__device__ __forceinline__ u64 pack2(float x, float y) {
    u64 d; asm("mov.b64 %0, {%1, %2};" : "=l"(d) : "f"(x), "f"(y)); return d;
}
__device__ __forceinline__ void unpack2(u64 v, float& x, float& y) {
    asm("mov.b64 {%0, %1}, %2;" : "=f"(x), "=f"(y) : "l"(v));
}

// ---------------- resize 1024->512 (antialiased) + zero counters ----------------
__global__ void k_resize(const float* __restrict__ full) {
    int t = blockIdx.x * blockDim.x + threadIdx.x;
    if (t < B) g_cnt[t] = 0;
    if (t >= B * HS * HS) return;
    int x = t % HS;
    int y = (t / HS) % HS;
    int b = t / (HS * HS);

    float wy[4], wx[4];
    int ry[4], rx[4];
    float sy = 0.f, sx = 0.f;
#pragma unroll
    for (int i = 0; i < 4; i++) {
        int r = 2 * y - 1 + i;
        float w = (i == 0 || i == 3) ? 0.25f : 0.75f;
        if (r < 0 || r >= Hf) w = 0.f;
        ry[i] = r < 0 ? 0 : (r >= Hf ? Hf - 1 : r);
        wy[i] = w; sy += w;
        int c = 2 * x - 1 + i;
        float w2 = (i == 0 || i == 3) ? 0.25f : 0.75f;
        if (c < 0 || c >= Wf) w2 = 0.f;
        rx[i] = c < 0 ? 0 : (c >= Wf ? Wf - 1 : c);
        wx[i] = w2; sx += w2;
    }
    float inv = 1.f / (sy * sx);
    const float* im = full + (size_t)b * Hf * Wf;
    float acc = 0.f;
#pragma unroll
    for (int i = 0; i < 4; i++) {
        const float* row = im + (size_t)ry[i] * Wf;
        float racc = 0.f;
#pragma unroll
        for (int j = 0; j < 4; j++) racc += wx[j] * row[rx[j]];
        acc += wy[i] * racc;
    }
    g_imgs[t] = acc * inv;
}

// ---------------- fused conv1+conv2 (unchanged from R2, it works) ----------------
#define SM_W1   0
#define SM_B1   800
#define SM_W2   832
#define SM_PART 1632
#define SM_HPL  9824
#define SM_FLOATS (9824 + 32 * 1296)

__global__ void __launch_bounds__(256) k_fused(
        const float* __restrict__ w1, const float* __restrict__ b1,
        const float* __restrict__ w2, const float* __restrict__ b2) {
    extern __shared__ float sm[];
    float* sw1 = sm + SM_W1;
    float* sb1 = sm + SM_B1;
    float* sw2 = sm + SM_W2;
    float* spart = sm + SM_PART;
    float* hpl = sm + SM_HPL;

    int tid = threadIdx.x;
    for (int i = tid; i < 800; i += 256) { sw1[i] = w1[i]; sw2[i] = w2[i]; }
    if (tid < 32) sb1[tid] = b1[tid];
    __syncthreads();

    int bx = blockIdx.x, by = blockIdx.y, b = blockIdx.z;
    const float* img = g_imgs + (size_t)b * HS * HS;

    for (int blk = tid; blk < 324; blk += 256) {
        int br = blk / 18, bc = blk % 18;
        int hy0 = by * 32 - 2 + 2 * br;
        int hx0 = bx * 32 - 2 + 2 * bc;
        int iy0 = 2 * hy0 - 1, ix0 = 2 * hx0 - 1;

        float p[7][7];
        bool inb = (iy0 >= 0) && (iy0 + 6 < HS) && (ix0 >= 0) && (ix0 + 6 < HS);
        if (inb) {
#pragma unroll
            for (int r = 0; r < 7; r++) {
                const float* row = img + (iy0 + r) * HS + ix0;
#pragma unroll
                for (int c = 0; c < 7; c++) p[r][c] = row[c];
            }
        } else {
#pragma unroll
            for (int r = 0; r < 7; r++) {
                int iy = iy0 + r;
                bool rv = (unsigned)iy < HS;
#pragma unroll
                for (int c = 0; c < 7; c++) {
                    int ix = ix0 + c;
                    p[r][c] = (rv && (unsigned)ix < HS) ? img[iy * HS + ix] : 0.f;
                }
            }
        }

        bool pv[4];
        pv[0] = ((unsigned)(hy0) < HC) && ((unsigned)(hx0) < HC);
        pv[1] = ((unsigned)(hy0) < HC) && ((unsigned)(hx0 + 1) < HC);
        pv[2] = ((unsigned)(hy0 + 1) < HC) && ((unsigned)(hx0) < HC);
        pv[3] = ((unsigned)(hy0 + 1) < HC) && ((unsigned)(hx0 + 1) < HC);

        for (int cg = 0; cg < 4; cg++) {
            u64 a0[4], a1[4], a2[4], a3[4];
#pragma unroll
            for (int cp = 0; cp < 4; cp++) {
                a0[cp] = 0ULL; a1[cp] = 0ULL; a2[cp] = 0ULL; a3[cp] = 0ULL;
            }
#pragma unroll
            for (int k = 0; k < 5; k++) {
#pragma unroll
                for (int l = 0; l < 5; l++) {
                    u64 v00 = pack2(p[k][l],         p[k][l]);
                    u64 v01 = pack2(p[k][l + 2],     p[k][l + 2]);
                    u64 v10 = pack2(p[k + 2][l],     p[k + 2][l]);
                    u64 v11 = pack2(p[k + 2][l + 2], p[k + 2][l + 2]);
                    const float* wp = sw1 + (k * 5 + l) * 32 + cg * 8;
#pragma unroll
                    for (int cp = 0; cp < 4; cp++) {
                        u64 wv = *reinterpret_cast<const u64*>(wp + cp * 2);
                        a0[cp] = ffma2(v00, wv, a0[cp]);
                        a1[cp] = ffma2(v01, wv, a1[cp]);
                        a2[cp] = ffma2(v10, wv, a2[cp]);
                        a3[cp] = ffma2(v11, wv, a3[cp]);
                    }
                }
            }
            int tr = 2 * br, tc = 2 * bc;
#pragma unroll
            for (int cp = 0; cp < 4; cp++) {
                int ch = cg * 8 + cp * 2;
                float bb0 = sb1[ch], bb1 = sb1[ch + 1];
                float lo, hi;
                float* h0p = hpl + ch * 1296;
                float* h1p = hpl + (ch + 1) * 1296;

                unpack2(a0[cp], lo, hi);
                h0p[tr * 36 + tc] = pv[0] ? fmaxf(lo + bb0, 0.f) : 0.f;
                h1p[tr * 36 + tc] = pv[0] ? fmaxf(hi + bb1, 0.f) : 0.f;
                unpack2(a1[cp], lo, hi);
                h0p[tr * 36 + tc + 1] = pv[1] ? fmaxf(lo + bb0, 0.f) : 0.f;
                h1p[tr * 36 + tc + 1] = pv[1] ? fmaxf(hi + bb1, 0.f) : 0.f;
                unpack2(a2[cp], lo, hi);
                h0p[(tr + 1) * 36 + tc] = pv[2] ? fmaxf(lo + bb0, 0.f) : 0.f;
                h1p[(tr + 1) * 36 + tc] = pv[2] ? fmaxf(hi + bb1, 0.f) : 0.f;
                unpack2(a3[cp], lo, hi);
                h0p[(tr + 1) * 36 + tc + 1] = pv[3] ? fmaxf(lo + bb0, 0.f) : 0.f;
                h1p[(tr + 1) * 36 + tc + 1] = pv[3] ? fmaxf(hi + bb1, 0.f) : 0.f;
            }
        }
    }
    __syncthreads();

    {
        int tx = tid & 31;
        int tg = tid >> 5;
        float acc[32];
#pragma unroll
        for (int r = 0; r < 32; r++) acc[r] = 0.f;

        for (int c = 0; c < 4; c++) {
            int ch = tg * 4 + c;
            const float* hp = hpl + ch * 1296 + tx;
            for (int dl = 0; dl < 5; dl++) {
                float t[36];
#pragma unroll
                for (int r = 0; r < 36; r++) t[r] = hp[r * 36 + dl];
#pragma unroll
                for (int dy = 0; dy < 5; dy++) {
                    float w = sw2[(dy * 5 + dl) * 32 + ch];
#pragma unroll
                    for (int jy = 0; jy < 32; jy++) acc[jy] += t[jy + dy] * w;
                }
            }
        }
#pragma unroll
        for (int r = 0; r < 32; r++) spart[tg * 1024 + r * 32 + tx] = acc[r];
    }
    __syncthreads();

    {
        float bias = b2[0];
        for (int i = tid; i < 1024; i += 256) {
            float s = bias;
#pragma unroll
            for (int g = 0; g < 8; g++) s += spart[g * 1024 + i];
            float z = 1.f / (1.f + expf(-s));
            int r = i >> 5, cc = i & 31;
            g_cms[((size_t)b * HC + (by * 32 + r)) * HC + (bx * 32 + cc)] = z;
        }
    }
}

// ---------------- NMS + warp-aggregated compaction ----------------
__global__ void k_nms() {
    int t = blockIdx.x * blockDim.x + threadIdx.x;   // exactly B*HC*HC threads
    float v = g_cms[t];
    int x = t % HC;
    int y = (t / HC) % HC;
    int b = t / (HC * HC);
    bool peak = false;
    if (v > THRESH) {
        peak = true;
        const float* c = g_cms + b * HC * HC;
#pragma unroll
        for (int dy = -1; dy <= 1; dy++)
#pragma unroll
            for (int dx = -1; dx <= 1; dx++) {
                if (dy == 0 && dx == 0) continue;
                int ny = y + dy, nx = x + dx;
                if ((unsigned)ny < HC && (unsigned)nx < HC)
                    if (c[ny * HC + nx] > v) peak = false;
            }
    }
    unsigned m = __ballot_sync(0xffffffffu, peak);   // warp all in same b
    if (peak) {
        int lane = threadIdx.x & 31;
        int leader = __ffs(m) - 1;
        int base = 0;
        if (lane == leader) base = atomicAdd(&g_cnt[b], __popc(m));
        base = __shfl_sync(m, base, leader);
        int off = __popc(m & ((1u << lane) - 1u));
        unsigned idx = (unsigned)(y * HC + x);
        u64 key = ((u64)__float_as_uint(v) << 32) | (0xFFFFFFFFu - idx);
        g_keys[b * HC * HC + base + off] = key;
    }
}

// ---------------- top-K from smem (shuffle reduce) + fused refine ----------------
__global__ void __launch_bounds__(512) k_topk(float* __restrict__ out, int out_size) {
    extern __shared__ u64 skeys[];               // NCAP keys = 128 KB
    __shared__ u64 wk[16];
    __shared__ int wp[16];
    __shared__ float sval[KTOP];
    __shared__ int   sidx[KTOP];

    int b = blockIdx.x, tid = threadIdx.x;
    int n = g_cnt[b];
    u64* gk = g_keys + b * HC * HC;
    bool use_sm = (n <= NCAP);
    if (use_sm) for (int i = tid; i < n; i += 512) skeys[i] = gk[i];
    u64* keys = use_sm ? skeys : gk;
    __syncthreads();

    int wid = tid >> 5, lane = tid & 31;

    for (int s = 0; s < KTOP; s++) {
        u64 best = 0ULL; int bp = -1;
        for (int i = tid; i < n; i += 512) {
            u64 k = keys[i];
            if (k > best) { best = k; bp = i; }
        }
#pragma unroll
        for (int o = 16; o > 0; o >>= 1) {
            u64 ok = __shfl_down_sync(0xffffffffu, best, o);
            int op = __shfl_down_sync(0xffffffffu, bp, o);
            if (ok > best) { best = ok; bp = op; }
        }
        if (lane == 0) { wk[wid] = best; wp[wid] = bp; }
        __syncthreads();
        if (wid == 0) {
            best = (lane < 16) ? wk[lane] : 0ULL;
            bp   = (lane < 16) ? wp[lane] : -1;
#pragma unroll
            for (int o = 8; o > 0; o >>= 1) {
                u64 ok = __shfl_down_sync(0xffffffffu, best, o);
                int op = __shfl_down_sync(0xffffffffu, bp, o);
                if (ok > best) { best = ok; bp = op; }
            }
            if (lane == 0) {
                if (best == 0ULL) {
                    sidx[s] = -1; sval[s] = 0.f;
                } else {
                    keys[bp] = 0ULL;
                    sval[s] = __uint_as_float((unsigned)(best >> 32));
                    sidx[s] = (int)(0xFFFFFFFFu - (unsigned)(best & 0xFFFFFFFFu));
                }
            }
        }
        __syncthreads();
    }

    // fused integral refinement + extras
    if (tid < KTOP) {
        int i = b * KTOP + tid;
        int idx = sidx[tid];
        float cx, cy, val, vf;
        if (idx < 0) {
            cx = (float)CROPS * 0.5f; cy = (float)CROPS * 0.5f; val = 0.f; vf = 0.f;
        } else {
            val = sval[tid]; vf = 1.f;
            int py = idx / HC, px = idx % HC;
            const float* c = g_cms + b * HC * HC;
            float gv = 0.f, sx = 0.f, sy = 0.f;
#pragma unroll
            for (int oy = -2; oy <= 2; oy++)
#pragma unroll
                for (int ox = -2; ox <= 2; ox++) {
                    int yy = py + oy, xx = px + ox;
                    float p = 0.f;
                    if ((unsigned)yy < HC && (unsigned)xx < HC) p = c[yy * HC + xx];
                    gv += p; sx += p * (float)ox; sy += p * (float)oy;
                }
            gv += 1e-12f;
            cx = ((float)px + sx / gv) * 4.f;
            cy = ((float)py + sy / gv) * 4.f;
        }
        g_cx[i] = cx; g_cy[i] = cy; g_validf[i] = vf;

        const int OFFC = B * KTOP * CROPS * CROPS;
        if (out_size >= OFFC + B * KTOP * 4) {
            out[OFFC + i * 2 + 0] = cx - (float)CROPS * 0.5f;
            out[OFFC + i * 2 + 1] = cy - (float)CROPS * 0.5f;
            out[OFFC + B * KTOP * 2 + i] = val;
            out[OFFC + B * KTOP * 3 + i] = vf;
        }
    }
}

// ---------------- bilinear 160x160 crops ----------------
__global__ void k_crop(const float* __restrict__ full, float* __restrict__ out) {
    int bk = blockIdx.x;
    int b = bk / KTOP;
    float cx = g_cx[bk], cy = g_cy[bk], vf = g_validf[bk];
    float bx = cx - (float)(CROPS - 1) * 0.5f;
    float by = cy - (float)(CROPS - 1) * 0.5f;
    const float* im = full + (size_t)b * Hf * Wf;
    float* o = out + (size_t)bk * CROPS * CROPS;

    for (int t = threadIdx.x; t < CROPS * CROPS; t += blockDim.x) {
        int i = t / CROPS, j = t % CROPS;
        float sy = by + (float)i;
        float sx = bx + (float)j;
        float y0 = floorf(sy), x0 = floorf(sx);
        float wy = sy - y0,   wx = sx - x0;
        int yi = (int)y0, xi = (int)x0;
        int y0c = min(max(yi, 0), Hf - 1);
        int y1c = min(max(yi + 1, 0), Hf - 1);
        int x0c = min(max(xi, 0), Wf - 1);
        int x1c = min(max(xi + 1, 0), Wf - 1);
        float a = im[y0c * Wf + x0c];
        float bb = im[y0c * Wf + x1c];
        float cc = im[y1c * Wf + x0c];
        float dd = im[y1c * Wf + x1c];
        float top = a * (1.f - wx) + bb * wx;
        float bot = cc * (1.f - wx) + dd * wx;
        float r = top * (1.f - wy) + bot * wy;
        bool inr = (sy >= 0.f) && (sy <= (float)(Hf - 1)) &&
                   (sx >= 0.f) && (sx <= (float)(Wf - 1));
        o[t] = (inr ? r : 0.f) * vf;
    }
}

// ---------------- launcher ----------------
extern "C" void kernel_launch(void* const* d_in, const int* in_sizes, int n_in,
                              void* d_out, int out_size) {
    const float* full = (const float*)d_in[0];
    const float* w1   = (const float*)d_in[1];
    const float* b1   = (const float*)d_in[2];
    const float* w2   = (const float*)d_in[3];
    const float* b2   = (const float*)d_in[4];
    float* out = (float*)d_out;

    const int smem_fused = SM_FLOATS * 4;
    cudaFuncSetAttribute(k_fused, cudaFuncAttributeMaxDynamicSharedMemorySize,
                         smem_fused);
    const int smem_topk = NCAP * 8;
    cudaFuncSetAttribute(k_topk, cudaFuncAttributeMaxDynamicSharedMemorySize,
                         smem_topk);

    k_resize<<<(B * HS * HS + 255) / 256, 256>>>(full);
    k_fused<<<dim3(HC / 32, HC / 32, B), 256, smem_fused>>>(w1, b1, w2, b2);
    k_nms<<<(B * HC * HC) / 256, 256>>>();
    k_topk<<<B, 512, smem_topk>>>(out, out_size);
    k_crop<<<B * KTOP, 256>>>(full, out);
}

// round 4
// speedup vs baseline: 1.6839x; 1.0432x over previous
#include <cuda_runtime.h>
#include <math.h>

#define B     16
#define Hf    1024
#define Wf    1024
#define HS    512
#define HC    256
#define NCH   32
#define KTOP  32
#define CROPS 160
#define THRESH 0.2f
#define NCAP  16384
#define CCAP  2048       // candidate cap for radix-select

typedef unsigned long long u64;

// ---------------- device scratch ----------------
__device__ float g_imgs[B * HS * HS];
__device__ float g_cms[B * HC * HC];
__device__ u64   g_keys[B * HC * HC];
__device__ int   g_cnt[B];
__device__ float g_cx[B * KTOP];
__device__ float g_cy[B * KTOP];
__device__ float g_validf[B * KTOP];

// ---------------- f32x2 helpers ----------------
__device__ __forceinline__ u64 ffma2(u64 a, u64 b, u64 c) {
    u64 d;
    asm("fma.rn.f32x2 %0, %1, %2, %3;" : "=l"(d) : "l"(a), "l"(b), "l"(c));
    return d;
}
__device__ __forceinline__ u64 pack2(float x, float y) {
    u64 d; asm("mov.b64 %0, {%1, %2};" : "=l"(d) : "f"(x), "f"(y)); return d;
}
__device__ __forceinline__ void unpack2(u64 v, float& x, float& y) {
    asm("mov.b64 {%0, %1}, %2;" : "=f"(x), "=f"(y) : "l"(v));
}

// ---------------- resize 1024->512 + zero counters ----------------
__global__ void k_resize(const float* __restrict__ full) {
    int t = blockIdx.x * blockDim.x + threadIdx.x;
    if (t < B) g_cnt[t] = 0;
    if (t >= B * HS * HS) return;
    int x = t % HS;
    int y = (t / HS) % HS;
    int b = t / (HS * HS);

    float wy[4], wx[4];
    int ry[4], rx[4];
    float sy = 0.f, sx = 0.f;
#pragma unroll
    for (int i = 0; i < 4; i++) {
        int r = 2 * y - 1 + i;
        float w = (i == 0 || i == 3) ? 0.25f : 0.75f;
        if (r < 0 || r >= Hf) w = 0.f;
        ry[i] = r < 0 ? 0 : (r >= Hf ? Hf - 1 : r);
        wy[i] = w; sy += w;
        int c = 2 * x - 1 + i;
        float w2 = (i == 0 || i == 3) ? 0.25f : 0.75f;
        if (c < 0 || c >= Wf) w2 = 0.f;
        rx[i] = c < 0 ? 0 : (c >= Wf ? Wf - 1 : c);
        wx[i] = w2; sx += w2;
    }
    float inv = 1.f / (sy * sx);
    const float* im = full + (size_t)b * Hf * Wf;
    float acc = 0.f;
#pragma unroll
    for (int i = 0; i < 4; i++) {
        const float* row = im + (size_t)ry[i] * Wf;
        float racc = 0.f;
#pragma unroll
        for (int j = 0; j < 4; j++) racc += wx[j] * row[rx[j]];
        acc += wy[i] * racc;
    }
    g_imgs[t] = acc * inv;
}

// ---------------- fused conv1+conv2 ----------------
// h tile stored TRANSPOSED (column-major, col stride 38) for vector LDS in step2.
#define HT_CS   38
#define HT_CH   (36 * HT_CS)     // 1368 floats per channel plane
#define SM_W1   0
#define SM_B1   800
#define SM_W2   832
#define SM_PART 1632
#define SM_HPL  9824
#define SM_FLOATS (9824 + 32 * HT_CH)   // 53600 floats = 214400 bytes

__global__ void __launch_bounds__(256, 1) k_fused(
        const float* __restrict__ w1, const float* __restrict__ b1,
        const float* __restrict__ w2, const float* __restrict__ b2) {
    extern __shared__ float sm[];
    float* sw1 = sm + SM_W1;
    float* sb1 = sm + SM_B1;
    float* sw2 = sm + SM_W2;
    float* spart = sm + SM_PART;
    float* hpl = sm + SM_HPL;

    int tid = threadIdx.x;
    for (int i = tid; i < 800; i += 256) { sw1[i] = w1[i]; sw2[i] = w2[i]; }
    if (tid < 32) sb1[tid] = b1[tid];
    __syncthreads();

    int bx = blockIdx.x, by = blockIdx.y, b = blockIdx.z;
    const float* img = g_imgs + (size_t)b * HS * HS;

    // ---- step 1: conv1 into transposed halo tile (36 rows x 36 cols x 32 ch) ----
    for (int blk = tid; blk < 324; blk += 256) {
        int br = blk / 18, bc = blk % 18;
        int hy0 = by * 32 - 2 + 2 * br;
        int hx0 = bx * 32 - 2 + 2 * bc;
        int iy0 = 2 * hy0 - 1, ix0 = 2 * hx0 - 1;

        float p[7][7];
        bool inb = (iy0 >= 0) && (iy0 + 6 < HS) && (ix0 >= 0) && (ix0 + 6 < HS);
        if (inb) {
#pragma unroll
            for (int r = 0; r < 7; r++) {
                const float* row = img + (iy0 + r) * HS + ix0;
#pragma unroll
                for (int c = 0; c < 7; c++) p[r][c] = row[c];
            }
        } else {
#pragma unroll
            for (int r = 0; r < 7; r++) {
                int iy = iy0 + r;
                bool rv = (unsigned)iy < HS;
#pragma unroll
                for (int c = 0; c < 7; c++) {
                    int ix = ix0 + c;
                    p[r][c] = (rv && (unsigned)ix < HS) ? img[iy * HS + ix] : 0.f;
                }
            }
        }

        bool pv[4];
        pv[0] = ((unsigned)(hy0) < HC) && ((unsigned)(hx0) < HC);
        pv[1] = ((unsigned)(hy0) < HC) && ((unsigned)(hx0 + 1) < HC);
        pv[2] = ((unsigned)(hy0 + 1) < HC) && ((unsigned)(hx0) < HC);
        pv[3] = ((unsigned)(hy0 + 1) < HC) && ((unsigned)(hx0 + 1) < HC);

        for (int cg = 0; cg < 4; cg++) {
            u64 a0[4], a1[4], a2[4], a3[4];
#pragma unroll
            for (int cp = 0; cp < 4; cp++) {
                a0[cp] = 0ULL; a1[cp] = 0ULL; a2[cp] = 0ULL; a3[cp] = 0ULL;
            }
#pragma unroll
            for (int k = 0; k < 5; k++) {
#pragma unroll
                for (int l = 0; l < 5; l++) {
                    u64 v00 = pack2(p[k][l],         p[k][l]);
                    u64 v01 = pack2(p[k][l + 2],     p[k][l + 2]);
                    u64 v10 = pack2(p[k + 2][l],     p[k + 2][l]);
                    u64 v11 = pack2(p[k + 2][l + 2], p[k + 2][l + 2]);
                    const float* wp = sw1 + (k * 5 + l) * 32 + cg * 8;
#pragma unroll
                    for (int cp = 0; cp < 4; cp++) {
                        u64 wv = *reinterpret_cast<const u64*>(wp + cp * 2);
                        a0[cp] = ffma2(v00, wv, a0[cp]);
                        a1[cp] = ffma2(v01, wv, a1[cp]);
                        a2[cp] = ffma2(v10, wv, a2[cp]);
                        a3[cp] = ffma2(v11, wv, a3[cp]);
                    }
                }
            }
            int tr = 2 * br, tc = 2 * bc;
#pragma unroll
            for (int cp = 0; cp < 4; cp++) {
                int ch = cg * 8 + cp * 2;
                float bb0 = sb1[ch], bb1 = sb1[ch + 1];
                float lo, hi;
                float* h0p = hpl + ch * HT_CH;
                float* h1p = hpl + (ch + 1) * HT_CH;

                unpack2(a0[cp], lo, hi);   // (tr, tc)
                h0p[tc * HT_CS + tr] = pv[0] ? fmaxf(lo + bb0, 0.f) : 0.f;
                h1p[tc * HT_CS + tr] = pv[0] ? fmaxf(hi + bb1, 0.f) : 0.f;
                unpack2(a1[cp], lo, hi);   // (tr, tc+1)
                h0p[(tc + 1) * HT_CS + tr] = pv[1] ? fmaxf(lo + bb0, 0.f) : 0.f;
                h1p[(tc + 1) * HT_CS + tr] = pv[1] ? fmaxf(hi + bb1, 0.f) : 0.f;
                unpack2(a2[cp], lo, hi);   // (tr+1, tc)
                h0p[tc * HT_CS + tr + 1] = pv[2] ? fmaxf(lo + bb0, 0.f) : 0.f;
                h1p[tc * HT_CS + tr + 1] = pv[2] ? fmaxf(hi + bb1, 0.f) : 0.f;
                unpack2(a3[cp], lo, hi);   // (tr+1, tc+1)
                h0p[(tc + 1) * HT_CS + tr + 1] = pv[3] ? fmaxf(lo + bb0, 0.f) : 0.f;
                h1p[(tc + 1) * HT_CS + tr + 1] = pv[3] ? fmaxf(hi + bb1, 0.f) : 0.f;
            }
        }
    }
    __syncthreads();

    // ---- step 2: conv2, packed f32x2, thread = (col tx, channel-group tg) ----
    {
        int tx = tid & 31;
        int tg = tid >> 5;
        u64 acc2[16];
#pragma unroll
        for (int k = 0; k < 16; k++) acc2[k] = 0ULL;

        for (int c = 0; c < 4; c++) {
            int ch = tg * 4 + c;
            const float* base = hpl + ch * HT_CH;
#pragma unroll
            for (int dl = 0; dl < 5; dl++) {
                const float2* col = (const float2*)(base + (tx + dl) * HT_CS);
                float2 t2[18];
#pragma unroll
                for (int k = 0; k < 18; k++) t2[k] = col[k];

                float w0 = sw2[(0 * 5 + dl) * 32 + ch];
                float w1v = sw2[(1 * 5 + dl) * 32 + ch];
                float w2v = sw2[(2 * 5 + dl) * 32 + ch];
                float w3v = sw2[(3 * 5 + dl) * 32 + ch];
                float w4v = sw2[(4 * 5 + dl) * 32 + ch];

                u64 wv0 = pack2(w0, w0);
                u64 wv2 = pack2(w2v, w2v);
                u64 wv4 = pack2(w4v, w4v);
#pragma unroll
                for (int k = 0; k < 16; k++) {
                    acc2[k] = ffma2(*(const u64*)&t2[k],     wv0, acc2[k]);
                    acc2[k] = ffma2(*(const u64*)&t2[k + 1], wv2, acc2[k]);
                    acc2[k] = ffma2(*(const u64*)&t2[k + 2], wv4, acc2[k]);
                }
                u64 wv1 = pack2(w1v, w1v);
                u64 wv3 = pack2(w3v, w3v);
#pragma unroll
                for (int k = 0; k < 16; k++) {
                    u64 q1 = pack2(t2[k].y,     t2[k + 1].x);
                    acc2[k] = ffma2(q1, wv1, acc2[k]);
                    u64 q3 = pack2(t2[k + 1].y, t2[k + 2].x);
                    acc2[k] = ffma2(q3, wv3, acc2[k]);
                }
            }
        }
#pragma unroll
        for (int k = 0; k < 16; k++) {
            float lo, hi;
            unpack2(acc2[k], lo, hi);
            spart[tg * 1024 + (2 * k) * 32 + tx]     = lo;
            spart[tg * 1024 + (2 * k + 1) * 32 + tx] = hi;
        }
    }
    __syncthreads();

    // ---- reduce 8 groups + bias + sigmoid ----
    {
        float bias = b2[0];
        for (int i = tid; i < 1024; i += 256) {
            float s = bias;
#pragma unroll
            for (int g = 0; g < 8; g++) s += spart[g * 1024 + i];
            float z = 1.f / (1.f + expf(-s));
            int r = i >> 5, cc = i & 31;
            g_cms[((size_t)b * HC + (by * 32 + r)) * HC + (bx * 32 + cc)] = z;
        }
    }
}

// ---------------- NMS + warp-aggregated compaction ----------------
__global__ void k_nms() {
    int t = blockIdx.x * blockDim.x + threadIdx.x;
    float v = g_cms[t];
    int x = t % HC;
    int y = (t / HC) % HC;
    int b = t / (HC * HC);
    bool peak = false;
    if (v > THRESH) {
        peak = true;
        const float* c = g_cms + b * HC * HC;
#pragma unroll
        for (int dy = -1; dy <= 1; dy++)
#pragma unroll
            for (int dx = -1; dx <= 1; dx++) {
                if (dy == 0 && dx == 0) continue;
                int ny = y + dy, nx = x + dx;
                if ((unsigned)ny < HC && (unsigned)nx < HC)
                    if (c[ny * HC + nx] > v) peak = false;
            }
    }
    unsigned m = __ballot_sync(0xffffffffu, peak);
    if (peak) {
        int lane = threadIdx.x & 31;
        int leader = __ffs(m) - 1;
        int base = 0;
        if (lane == leader) base = atomicAdd(&g_cnt[b], __popc(m));
        base = __shfl_sync(m, base, leader);
        int off = __popc(m & ((1u << lane) - 1u));
        unsigned idx = (unsigned)(y * HC + x);
        u64 key = ((u64)__float_as_uint(v) << 32) | (0xFFFFFFFFu - idx);
        g_keys[b * HC * HC + base + off] = key;
    }
}

// ---------------- radix-select top-K + fused refine ----------------
// All stored key values are in (0.2, 1): float bits share top 3 bits, so
// bin = bits[28:15] (14 bits) is monotonic in value.
__device__ __forceinline__ int key_bin(u64 k) {
    return (int)((k >> 47) & 0x3FFF);
}

__global__ void __launch_bounds__(512) k_topk(float* __restrict__ out, int out_size) {
    extern __shared__ char smraw[];
    u64* skeys = (u64*)smraw;                         // 16384 * 8 = 131072
    int* hist  = (int*)(smraw + 131072);              // 16384 * 4 = 65536
    u64* cand  = (u64*)(smraw + 131072 + 65536);      // 2048 * 8 = 16384
    __shared__ int ss[128];    // coarse suffix
    __shared__ int sc[128];    // fine suffix
    __shared__ int sG, sT, s_m;
    __shared__ float sval[KTOP];
    __shared__ int   sidx[KTOP];
    __shared__ u64 wk[16];
    __shared__ int wp[16];

    int b = blockIdx.x, tid = threadIdx.x;
    int n = g_cnt[b];
    u64* gk = g_keys + b * HC * HC;
    bool use_sm = (n <= NCAP);

    for (int i = tid; i < 16384; i += 512) hist[i] = 0;
    if (tid == 0) { sG = -1; s_m = 0; }
    __syncthreads();

    if (use_sm) {
        for (int i = tid; i < n; i += 512) {
            u64 k = gk[i];
            skeys[i] = k;
            atomicAdd(&hist[key_bin(k)], 1);
        }
    } else {
        for (int i = tid; i < n; i += 512)
            atomicAdd(&hist[key_bin(gk[i])], 1);
    }
    u64* keys = use_sm ? skeys : gk;
    __syncthreads();

    // coarse counts: 128 groups of 128 bins
    if (tid < 128) {
        int s = 0;
        for (int j = 0; j < 128; j++) s += hist[tid * 128 + j];
        ss[tid] = s;
    }
    __syncthreads();
    // inclusive suffix scan of ss (from top)
    for (int off = 1; off < 128; off <<= 1) {
        int v = 0;
        if (tid < 128) { v = ss[tid]; if (tid + off < 128) v += ss[tid + off]; }
        __syncthreads();
        if (tid < 128) ss[tid] = v;
        __syncthreads();
    }
    // threshold group: max g with suffix(g) >= KTOP
    if (tid < 128 && ss[tid] >= KTOP && (tid + 1 >= 128 || ss[tid + 1] < KTOP))
        sG = tid;
    __syncthreads();
    int G = sG;
    if (G < 0) {
        if (tid == 0) sT = 0;           // total < KTOP: all keys are candidates
    } else {
        int basec = (G + 1 < 128) ? ss[G + 1] : 0;
        if (tid < 128) sc[tid] = hist[G * 128 + tid];
        __syncthreads();
        for (int off = 1; off < 128; off <<= 1) {
            int v = 0;
            if (tid < 128) { v = sc[tid]; if (tid + off < 128) v += sc[tid + off]; }
            __syncthreads();
            if (tid < 128) sc[tid] = v;
            __syncthreads();
        }
        if (tid < 128 && basec + sc[tid] >= KTOP &&
            (tid + 1 >= 128 || basec + sc[tid + 1] < KTOP))
            sT = G * 128 + tid;
    }
    __syncthreads();
    int T = sT;

    // compact candidates (bin >= T)
    for (int i = tid; i < n; i += 512) {
        u64 k = keys[i];
        if (key_bin(k) >= T) {
            int p = atomicAdd(&s_m, 1);
            if (p < CCAP) cand[p] = k;
        }
    }
    __syncthreads();
    int m = s_m;
    int wid = tid >> 5, lane = tid & 31;

    if (m <= CCAP) {
        // warp-0 extraction over candidates (no block barriers)
        if (wid == 0) {
            for (int s = 0; s < KTOP; s++) {
                u64 best = 0ULL; int bp = -1;
                for (int i = lane; i < m; i += 32) {
                    u64 k = cand[i];
                    if (k > best) { best = k; bp = i; }
                }
#pragma unroll
                for (int o = 16; o > 0; o >>= 1) {
                    u64 ok = __shfl_down_sync(0xffffffffu, best, o);
                    int op = __shfl_down_sync(0xffffffffu, bp, o);
                    if (ok > best) { best = ok; bp = op; }
                }
                if (lane == 0) {
                    if (best == 0ULL) {
                        sidx[s] = -1; sval[s] = 0.f;
                    } else {
                        cand[bp] = 0ULL;
                        sval[s] = __uint_as_float((unsigned)(best >> 32));
                        sidx[s] = (int)(0xFFFFFFFFu - (unsigned)(best & 0xFFFFFFFFu));
                    }
                }
                __syncwarp();
            }
        }
        __syncthreads();
    } else {
        // fallback: block-wide extraction over all keys (pathological only)
        for (int s = 0; s < KTOP; s++) {
            u64 best = 0ULL; int bp = -1;
            for (int i = tid; i < n; i += 512) {
                u64 k = keys[i];
                if (k > best) { best = k; bp = i; }
            }
#pragma unroll
            for (int o = 16; o > 0; o >>= 1) {
                u64 ok = __shfl_down_sync(0xffffffffu, best, o);
                int op = __shfl_down_sync(0xffffffffu, bp, o);
                if (ok > best) { best = ok; bp = op; }
            }
            if (lane == 0) { wk[wid] = best; wp[wid] = bp; }
            __syncthreads();
            if (wid == 0) {
                best = (lane < 16) ? wk[lane] : 0ULL;
                bp   = (lane < 16) ? wp[lane] : -1;
#pragma unroll
                for (int o = 8; o > 0; o >>= 1) {
                    u64 ok = __shfl_down_sync(0xffffffffu, best, o);
                    int op = __shfl_down_sync(0xffffffffu, bp, o);
                    if (ok > best) { best = ok; bp = op; }
                }
                if (lane == 0) {
                    if (best == 0ULL) {
                        sidx[s] = -1; sval[s] = 0.f;
                    } else {
                        keys[bp] = 0ULL;
                        sval[s] = __uint_as_float((unsigned)(best >> 32));
                        sidx[s] = (int)(0xFFFFFFFFu - (unsigned)(best & 0xFFFFFFFFu));
                    }
                }
            }
            __syncthreads();
        }
    }

    // fused integral refinement + extras
    if (tid < KTOP) {
        int i = b * KTOP + tid;
        int idx = sidx[tid];
        float cx, cy, val, vf;
        if (idx < 0) {
            cx = (float)CROPS * 0.5f; cy = (float)CROPS * 0.5f; val = 0.f; vf = 0.f;
        } else {
            val = sval[tid]; vf = 1.f;
            int py = idx / HC, px = idx % HC;
            const float* c = g_cms + b * HC * HC;
            float gv = 0.f, sx = 0.f, sy = 0.f;
#pragma unroll
            for (int oy = -2; oy <= 2; oy++)
#pragma unroll
                for (int ox = -2; ox <= 2; ox++) {
                    int yy = py + oy, xx = px + ox;
                    float p = 0.f;
                    if ((unsigned)yy < HC && (unsigned)xx < HC) p = c[yy * HC + xx];
                    gv += p; sx += p * (float)ox; sy += p * (float)oy;
                }
            gv += 1e-12f;
            cx = ((float)px + sx / gv) * 4.f;
            cy = ((float)py + sy / gv) * 4.f;
        }
        g_cx[i] = cx; g_cy[i] = cy; g_validf[i] = vf;

        const int OFFC = B * KTOP * CROPS * CROPS;
        if (out_size >= OFFC + B * KTOP * 4) {
            out[OFFC + i * 2 + 0] = cx - (float)CROPS * 0.5f;
            out[OFFC + i * 2 + 1] = cy - (float)CROPS * 0.5f;
            out[OFFC + B * KTOP * 2 + i] = val;
            out[OFFC + B * KTOP * 3 + i] = vf;
        }
    }
}

// ---------------- bilinear 160x160 crops ----------------
__global__ void k_crop(const float* __restrict__ full, float* __restrict__ out) {
    int bk = blockIdx.x;
    int b = bk / KTOP;
    float cx = g_cx[bk], cy = g_cy[bk], vf = g_validf[bk];
    float bx = cx - (float)(CROPS - 1) * 0.5f;
    float by = cy - (float)(CROPS - 1) * 0.5f;
    const float* im = full + (size_t)b * Hf * Wf;
    float* o = out + (size_t)bk * CROPS * CROPS;

    for (int t = threadIdx.x; t < CROPS * CROPS; t += blockDim.x) {
        int i = t / CROPS, j = t % CROPS;
        float sy = by + (float)i;
        float sx = bx + (float)j;
        float y0 = floorf(sy), x0 = floorf(sx);
        float wy = sy - y0,   wx = sx - x0;
        int yi = (int)y0, xi = (int)x0;
        int y0c = min(max(yi, 0), Hf - 1);
        int y1c = min(max(yi + 1, 0), Hf - 1);
        int x0c = min(max(xi, 0), Wf - 1);
        int x1c = min(max(xi + 1, 0), Wf - 1);
        float a = im[y0c * Wf + x0c];
        float bb = im[y0c * Wf + x1c];
        float cc = im[y1c * Wf + x0c];
        float dd = im[y1c * Wf + x1c];
        float top = a * (1.f - wx) + bb * wx;
        float bot = cc * (1.f - wx) + dd * wx;
        float r = top * (1.f - wy) + bot * wy;
        bool inr = (sy >= 0.f) && (sy <= (float)(Hf - 1)) &&
                   (sx >= 0.f) && (sx <= (float)(Wf - 1));
        o[t] = (inr ? r : 0.f) * vf;
    }
}

// ---------------- launcher ----------------
extern "C" void kernel_launch(void* const* d_in, const int* in_sizes, int n_in,
                              void* d_out, int out_size) {
    const float* full = (const float*)d_in[0];
    const float* w1   = (const float*)d_in[1];
    const float* b1   = (const float*)d_in[2];
    const float* w2   = (const float*)d_in[3];
    const float* b2   = (const float*)d_in[4];
    float* out = (float*)d_out;

    const int smem_fused = SM_FLOATS * 4;                 // 214400
    cudaFuncSetAttribute(k_fused, cudaFuncAttributeMaxDynamicSharedMemorySize,
                         smem_fused);
    const int smem_topk = 131072 + 65536 + CCAP * 8;      // 212992
    cudaFuncSetAttribute(k_topk, cudaFuncAttributeMaxDynamicSharedMemorySize,
                         smem_topk);

    k_resize<<<(B * HS * HS + 255) / 256, 256>>>(full);
    k_fused<<<dim3(HC / 32, HC / 32, B), 256, smem_fused>>>(w1, b1, w2, b2);
    k_nms<<<(B * HC * HC) / 256, 256>>>();
    k_topk<<<B, 512, smem_topk>>>(out, out_size);
    k_crop<<<B * KTOP, 256>>>(full, out);
}